// round 15
// baseline (speedup 1.0000x reference)
#include <cuda_runtime.h>
#include <cuda_bf16.h>
#include <math.h>
#include <stdint.h>

#define CH 256
#define NBATCH 64
#define HW 1024
#define MTOT 65536
#define EPSV 1e-5f
#define T_ITERS 10
#define NCTA 64

// ---------------- device scratch ----------------
__device__ float g_mean[CH];
__device__ float g_msum[CH*NBATCH];
__device__ float g_bias[CH];
__device__ float g_Sig [CH*CH];
__device__ float g_M   [CH*CH];
__device__ float g_part[192*16384];
__device__ __align__(16) __nv_bfloat16 g_xhi[64L*256*1024];
__device__ __align__(16) __nv_bfloat16 g_xlo[64L*256*1024];
__device__ __align__(16) __nv_bfloat16 g_Mhi [CH*CH], g_Mlo [CH*CH];
__device__ __align__(16) __nv_bfloat16 g_Phi [CH*CH], g_Plo [CH*CH];
__device__ __align__(16) __nv_bfloat16 g_T1hi[CH*CH], g_T1lo[CH*CH];
__device__ __align__(16) __nv_bfloat16 g_T2hi[CH*CH], g_T2lo[CH*CH];
__device__ __align__(16) __nv_bfloat16 g_SNhi[CH*CH], g_SNlo[CH*CH];
__device__ __align__(16) __nv_bfloat16 g_Rhi [CH*CH], g_Rlo [CH*CH];
__device__ unsigned g_bar_cnt;

// ---------------- helpers ----------------
__device__ __forceinline__ uint32_t smem_u32(const void* p) {
    uint32_t a;
    asm("{ .reg .u64 t; cvta.to.shared.u64 t, %1; cvt.u32.u64 %0, t; }" : "=r"(a) : "l"(p));
    return a;
}
__device__ __forceinline__ void ldm_x4(uint32_t* r, uint32_t addr) {
    asm volatile("ldmatrix.sync.aligned.m8n8.x4.shared.b16 {%0,%1,%2,%3}, [%4];"
        : "=r"(r[0]), "=r"(r[1]), "=r"(r[2]), "=r"(r[3]) : "r"(addr));
}
__device__ __forceinline__ void ldm_x2(uint32_t* r, uint32_t addr) {
    asm volatile("ldmatrix.sync.aligned.m8n8.x2.shared.b16 {%0,%1}, [%2];"
        : "=r"(r[0]), "=r"(r[1]) : "r"(addr));
}
__device__ __forceinline__ void ldm_x2t(uint32_t* r, uint32_t addr) {
    asm volatile("ldmatrix.sync.aligned.m8n8.x2.trans.shared.b16 {%0,%1}, [%2];"
        : "=r"(r[0]), "=r"(r[1]) : "r"(addr));
}
__device__ __forceinline__ void mma_bf16(float* c, const uint32_t* a, const uint32_t* b) {
    asm volatile("mma.sync.aligned.m16n8k16.row.col.f32.bf16.bf16.f32 "
        "{%0,%1,%2,%3}, {%4,%5,%6,%7}, {%8,%9}, {%0,%1,%2,%3};"
        : "+f"(c[0]), "+f"(c[1]), "+f"(c[2]), "+f"(c[3])
        : "r"(a[0]), "r"(a[1]), "r"(a[2]), "r"(a[3]), "r"(b[0]), "r"(b[1]));
}
__device__ __forceinline__ void cp16(uint32_t dst, const void* src) {
    asm volatile("cp.async.cg.shared.global [%0], [%1], 16;" :: "r"(dst), "l"(src));
}
__device__ __forceinline__ void cp_commit() { asm volatile("cp.async.commit_group;" ::: "memory"); }
template<int N> __device__ __forceinline__ void cp_wait() {
    asm volatile("cp.async.wait_group %0;" :: "n"(N) : "memory");
}
__device__ __forceinline__ void bfsplit(float v, __nv_bfloat16& h, __nv_bfloat16& l) {
    h = __float2bfloat16(v);
    l = __float2bfloat16(v - __bfloat162float(h));
}

// ---------------- monotonic grid barrier: release/acquire ----------------
struct GBar { unsigned nbar = 0; };
__device__ __forceinline__ void gbar(GBar& gb) {
    __syncthreads();
    gb.nbar++;
    if (threadIdx.x == 0) {
        unsigned target = gb.nbar * NCTA;
        asm volatile("red.release.gpu.add.u32 [%0], 1;" :: "l"(&g_bar_cnt) : "memory");
        unsigned v;
        do {
            asm volatile("ld.acquire.gpu.u32 %0, [%1];" : "=r"(v) : "l"(&g_bar_cnt) : "memory");
        } while (v < target);
    }
    __syncthreads();
}

// ---------------- fused convert + Gram ----------------
// Reads fp32 X directly (same bytes/elem as hi+lo), converts per K-chunk in smem,
// does the 3-pass bf16 MMA, AND (q=0, q=2) writes g_xhi/g_xlo + per-(c,n) sums.
// smem: fp32 staging A[2 stages] B[2 stages] (272B rows) + bf16 tiles Ah/Al/Bh/Bl (144B rows)
#define FST 34816u                       // 128 rows * 272 B fp32 staging
#define GT  18432u                       // 128 rows * 144 B bf16 tile
#define TB  (4u*FST)                     // tile base = 139264
#define GF_SMEM (4u*FST + 4u*GT)         // 212992
__global__ void __launch_bounds__(512, 1) k_gram_fused(const float* __restrict__ X) {
    extern __shared__ char sm[];
    int q = blockIdx.x, n = blockIdx.y;
    int ci0 = (q == 2) ? 128 : 0;
    int cj0 = (q == 0) ? 0 : 128;
    bool diag = (q != 1);
    int tid = threadIdx.x, lane = tid & 31, wid = tid >> 5;
    int wm = wid >> 2, wn = wid & 3;
    uint32_t sbase = smem_u32(sm);
    if (q == 0 && n == 0 && tid == 0) g_bar_cnt = 0;

    int row = tid >> 2, qL = tid & 3;
    const float* gA = X + ((size_t)n*CH + ci0 + row)*HW + qL*16;
    const float* gB = X + ((size_t)n*CH + cj0 + row)*HW + qL*16;

    float acc[2][4][4];
    #pragma unroll
    for (int a = 0; a < 2; a++)
        #pragma unroll
        for (int b = 0; b < 4; b++)
            #pragma unroll
            for (int k = 0; k < 4; k++) acc[a][b][k] = 0.f;
    float msum = 0.f;

    auto prefetch = [&](int kb, int st) {
        int pb = kb*64;
        uint32_t dA = sbase + st*FST + row*272 + qL*64;
        #pragma unroll
        for (int j = 0; j < 4; j++) cp16(dA + j*16, gA + pb + j*4);
        if (!diag) {
            uint32_t dB = sbase + 2*FST + st*FST + row*272 + qL*64;
            #pragma unroll
            for (int j = 0; j < 4; j++) cp16(dB + j*16, gB + pb + j*4);
        }
    };

    prefetch(0, 0); cp_commit();
    prefetch(1, 1); cp_commit();
    for (int kb = 0; kb < 16; kb++) {
        int cur = kb & 1;
        if (kb < 15) cp_wait<1>(); else cp_wait<0>();
        __syncthreads();

        // convert A (and B if offdiag) from fp32 staging to hi/lo tiles (+ STG + msum for q0/q2)
        {
            const char* srcA = sm + cur*FST + row*272 + qL*64;
            float f[16];
            #pragma unroll
            for (int j = 0; j < 4; j++) {
                float4 v = *(const float4*)(srcA + j*16);
                f[j*4+0]=v.x; f[j*4+1]=v.y; f[j*4+2]=v.z; f[j*4+3]=v.w;
            }
            uint32_t hw[8], lw[8];
            #pragma unroll
            for (int j = 0; j < 8; j++) {
                __nv_bfloat16 h0,l0,h1,l1;
                bfsplit(f[2*j],   h0, l0);
                bfsplit(f[2*j+1], h1, l1);
                __nv_bfloat162 hp(h0,h1), lp(l0,l1);
                hw[j] = *(uint32_t*)&hp; lw[j] = *(uint32_t*)&lp;
            }
            char* dh = sm + TB + row*144 + qL*32;
            char* dl = dh + GT;
            *(uint4*)(dh)      = make_uint4(hw[0],hw[1],hw[2],hw[3]);
            *(uint4*)(dh + 16) = make_uint4(hw[4],hw[5],hw[6],hw[7]);
            *(uint4*)(dl)      = make_uint4(lw[0],lw[1],lw[2],lw[3]);
            *(uint4*)(dl + 16) = make_uint4(lw[4],lw[5],lw[6],lw[7]);
            if (diag) {
                size_t go = ((size_t)n*CH + ci0 + row)*HW + kb*64 + qL*16;
                *(uint4*)(g_xhi + go)     = make_uint4(hw[0],hw[1],hw[2],hw[3]);
                *(uint4*)(g_xhi + go + 8) = make_uint4(hw[4],hw[5],hw[6],hw[7]);
                *(uint4*)(g_xlo + go)     = make_uint4(lw[0],lw[1],lw[2],lw[3]);
                *(uint4*)(g_xlo + go + 8) = make_uint4(lw[4],lw[5],lw[6],lw[7]);
                #pragma unroll
                for (int j = 0; j < 16; j++) msum += f[j];
            } else {
                const char* srcB = sm + 2*FST + cur*FST + row*272 + qL*64;
                float fb[16];
                #pragma unroll
                for (int j = 0; j < 4; j++) {
                    float4 v = *(const float4*)(srcB + j*16);
                    fb[j*4+0]=v.x; fb[j*4+1]=v.y; fb[j*4+2]=v.z; fb[j*4+3]=v.w;
                }
                uint32_t bhw[8], blw[8];
                #pragma unroll
                for (int j = 0; j < 8; j++) {
                    __nv_bfloat16 h0,l0,h1,l1;
                    bfsplit(fb[2*j],   h0, l0);
                    bfsplit(fb[2*j+1], h1, l1);
                    __nv_bfloat162 hp(h0,h1), lp(l0,l1);
                    bhw[j] = *(uint32_t*)&hp; blw[j] = *(uint32_t*)&lp;
                }
                char* dbh = sm + TB + 2*GT + row*144 + qL*32;
                char* dbl = dbh + GT;
                *(uint4*)(dbh)      = make_uint4(bhw[0],bhw[1],bhw[2],bhw[3]);
                *(uint4*)(dbh + 16) = make_uint4(bhw[4],bhw[5],bhw[6],bhw[7]);
                *(uint4*)(dbl)      = make_uint4(blw[0],blw[1],blw[2],blw[3]);
                *(uint4*)(dbl + 16) = make_uint4(blw[4],blw[5],blw[6],blw[7]);
            }
        }
        __syncthreads();
        if (kb + 2 < 16) { prefetch(kb+2, cur); cp_commit(); }

        uint32_t tb = sbase + TB;
        uint32_t bb = tb + (diag ? 0 : 2*GT);
        #pragma unroll
        for (int ks = 0; ks < 4; ks++) {
            int k0 = ks*16;
            uint32_t ah[2][4], al[2][4], bh[4][2], bl[4][2];
            int ar = lane & 15, ac = (lane >> 4) * 8;
            #pragma unroll
            for (int mt = 0; mt < 2; mt++) {
                uint32_t ao = tb + (wm*32 + mt*16 + ar)*144 + (k0 + ac)*2;
                ldm_x4(ah[mt], ao);
                ldm_x4(al[mt], ao + GT);
            }
            int br = lane & 7, bc = ((lane >> 3) & 1) * 8;
            #pragma unroll
            for (int nt = 0; nt < 4; nt++) {
                uint32_t bo = bb + (wn*32 + nt*8 + br)*144 + (k0 + bc)*2;
                ldm_x2(bh[nt], bo);
                ldm_x2(bl[nt], bo + GT);
            }
            #pragma unroll
            for (int mt = 0; mt < 2; mt++)
                #pragma unroll
                for (int nt = 0; nt < 4; nt++) {
                    mma_bf16(acc[mt][nt], ah[mt], bh[nt]);
                    mma_bf16(acc[mt][nt], ah[mt], bl[nt]);
                    mma_bf16(acc[mt][nt], al[mt], bh[nt]);
                }
        }
        __syncthreads();
    }
    // per-(c,n) sums (q0 covers c0-127, q2 covers c128-255)
    if (diag) {
        msum += __shfl_xor_sync(~0u, msum, 1);
        msum += __shfl_xor_sync(~0u, msum, 2);
        if (qL == 0) g_msum[(ci0 + row)*NBATCH + n] = msum;
    }
    float* pout = g_part + ((size_t)q*64 + n)*16384;
    int rg = lane >> 2, cg = (lane & 3)*2;
    #pragma unroll
    for (int mt = 0; mt < 2; mt++)
        #pragma unroll
        for (int nt = 0; nt < 4; nt++) {
            int r0 = wm*32 + mt*16 + rg, c0 = wn*32 + nt*8 + cg;
            *(float2*)(pout + r0*128 + c0)     = make_float2(acc[mt][nt][0], acc[mt][nt][1]);
            *(float2*)(pout + (r0+8)*128 + c0) = make_float2(acc[mt][nt][2], acc[mt][nt][3]);
        }
}

// ---------------- pipelined tensor tile matmul for the solver (3-stage, 256 thr) ----------------
template<int TM>
__device__ __forceinline__ void nt_mm2(
    const __nv_bfloat16* __restrict__ Ah, const __nv_bfloat16* __restrict__ Al,
    const __nv_bfloat16* __restrict__ Bh, const __nv_bfloat16* __restrict__ Bl,
    __nv_bfloat16* __restrict__ Chi, __nv_bfloat16* __restrict__ Clo,
    int tr, int tc, int mode, float snorm, __nv_bfloat16* ns)
{
    constexpr int SA  = TM*72;
    constexpr int SB  = 64*40;
    constexpr int STB = (2*SA + 2*SB)*2;
    constexpr int NT  = (TM == 64) ? 2 : 1;
    constexpr int WNW = (TM == 64) ? 16 : 8;
    int tid = threadIdx.x, lane = tid & 31, wid = tid >> 5;
    int wm = (TM == 64) ? (wid >> 1) : (wid >> 2);
    int wn = (TM == 64) ? (wid & 1)  : (wid & 3);
    uint32_t base = smem_u32(ns);

    float acc[NT][4];
    #pragma unroll
    for (int nt = 0; nt < NT; nt++)
        #pragma unroll
        for (int k = 0; k < 4; k++) acc[nt][k] = 0.f;

    int brow = tid >> 2, bcol = tid & 3;

    auto stage = [&](int kb, int st) {
        uint32_t sb = base + st*STB;
        #pragma unroll
        for (int c = 0; c < TM*8; c += 256) {
            int cc = c + tid;
            int r = cc >> 3, col = cc & 7;
            uint32_t d = sb + r*144 + col*16;
            cp16(d,        Ah + (tr + r)*256 + kb + col*8);
            cp16(d + SA*2, Al + (tr + r)*256 + kb + col*8);
        }
        uint32_t dB = sb + 2*(SA*2) + brow*80 + bcol*16;
        cp16(dB,        Bh + (kb + brow)*256 + tc + bcol*8);
        cp16(dB + SB*2, Bl + (kb + brow)*256 + tc + bcol*8);
    };

    stage(0, 0); cp_commit();
    stage(64, 1); cp_commit();
    for (int kb = 0; kb < 4; kb++) {
        int cur = kb % 3;
        if (kb < 3) cp_wait<1>(); else cp_wait<0>();
        __syncthreads();
        if (kb + 2 < 4) { stage((kb+2)*64, (kb+2) % 3); cp_commit(); }
        uint32_t sb  = base + cur*STB;
        uint32_t sbB = sb + 2*(SA*2);
        #pragma unroll
        for (int ks = 0; ks < 4; ks++) {
            int k0 = ks*16;
            uint32_t ah[4], al[4], bh[NT][2], bl[NT][2];
            uint32_t ao = sb + (wm*16 + (lane & 15))*144 + (k0 + (lane >> 4)*8)*2;
            ldm_x4(ah, ao);
            ldm_x4(al, ao + SA*2);
            #pragma unroll
            for (int nt = 0; nt < NT; nt++) {
                uint32_t bo = sbB + (k0 + (lane & 15))*80 + (wn*WNW + nt*8)*2;
                ldm_x2t(bh[nt], bo);
                ldm_x2t(bl[nt], bo + SB*2);
            }
            #pragma unroll
            for (int nt = 0; nt < NT; nt++) {
                mma_bf16(acc[nt], ah, bh[nt]);
                mma_bf16(acc[nt], ah, bl[nt]);
                mma_bf16(acc[nt], al, bh[nt]);
            }
        }
    }
    int rg = lane >> 2, cg = (lane & 3)*2;
    #pragma unroll
    for (int nt = 0; nt < NT; nt++) {
        int col = tc + wn*WNW + nt*8 + cg;
        #pragma unroll
        for (int half = 0; half < 2; half++) {
            int r = tr + wm*16 + rg + half*8;
            float v0 = acc[nt][half*2], v1 = acc[nt][half*2+1];
            int idx = r*256 + col;
            if (mode == 1) {
                __nv_bfloat162 ph = *(__nv_bfloat162*)(g_Phi + idx);
                __nv_bfloat162 pl = *(__nv_bfloat162*)(g_Plo + idx);
                float p0 = __bfloat162float(ph.x) + __bfloat162float(pl.x);
                float p1 = __bfloat162float(ph.y) + __bfloat162float(pl.y);
                v0 = 1.5f*p0 - 0.5f*v0;
                v1 = 1.5f*p1 - 0.5f*v1;
            } else if (mode == 2) {
                v0 *= snorm; v1 *= snorm;
                *(float2*)(g_M + idx) = make_float2(v0, v1);
            }
            __nv_bfloat16 h0, l0, h1, l1;
            bfsplit(v0, h0, l0); bfsplit(v1, h1, l1);
            *(__nv_bfloat162*)(Chi + idx) = __nv_bfloat162(h0, h1);
            *(__nv_bfloat162*)(Clo + idx) = __nv_bfloat162(l0, l1);
        }
    }
}

#define SOLVER_SMEM (3*((2*64*72 + 2*64*40)*2))

// ---------------- persistent solver (256 threads) ----------------
__global__ void __launch_bounds__(256) k_solver(const float* __restrict__ rot) {
    extern __shared__ __align__(16) char dynsm[];
    __nv_bfloat16* ns = (__nv_bfloat16*)dynsm;
    int cta = blockIdx.x, tid = threadIdx.x, lane = tid & 31, wid = tid >> 5;
    __shared__ float red[256];
    __shared__ float s_scal[2];
    GBar gb;

    // phase 0: mean reduce
    {
        int wg = cta*8 + wid;
        if (wg < 256) {
            float s = g_msum[wg*NBATCH + lane] + g_msum[wg*NBATCH + 32 + lane];
            #pragma unroll
            for (int o = 16; o > 0; o >>= 1) s += __shfl_xor_sync(~0u, s, o);
            if (lane == 0) g_mean[wg] = s * (1.f / (float)MTOT);
        }
    }
    gbar(gb);

    // phase 1: sigfin
    {
        int idx4 = cta*256 + tid;
        int a = idx4 >> 6, b = (idx4 & 63) * 4;
        float4 s4 = make_float4(0.f, 0.f, 0.f, 0.f);
        if (a < 128 || b >= 128) {
            int q = (a < 128) ? ((b < 128) ? 0 : 1) : 2;
            const float* pp = g_part + (size_t)q*64*16384 + (a & 127)*128 + (b & 127);
            #pragma unroll 4
            for (int t = 0; t < 64; t++) {
                float4 v = __ldcg((const float4*)(pp + (size_t)t*16384));
                s4.x += v.x; s4.y += v.y; s4.z += v.z; s4.w += v.w;
            }
        } else {
            const float* pp = g_part + (size_t)1*64*16384 + b*128 + (a - 128);
            #pragma unroll 4
            for (int t = 0; t < 64; t++) {
                const float* bb = pp + (size_t)t*16384;
                s4.x += __ldcg(bb); s4.y += __ldcg(bb+128); s4.z += __ldcg(bb+256); s4.w += __ldcg(bb+384);
            }
        }
        float ma = g_mean[a];
        float4 mb = *(const float4*)(g_mean + b);
        float4 v = make_float4(s4.x*(1.f/(float)MTOT) - ma*mb.x,
                               s4.y*(1.f/(float)MTOT) - ma*mb.y,
                               s4.z*(1.f/(float)MTOT) - ma*mb.z,
                               s4.w*(1.f/(float)MTOT) - ma*mb.w);
        if (a == b)   v.x += EPSV;
        if (a == b+1) v.y += EPSV;
        if (a == b+2) v.z += EPSV;
        if (a == b+3) v.w += EPSV;
        *(float4*)(g_Sig + a*256 + b) = v;
    }
    gbar(gb);

    // phase 2: trace + init SigN hi/lo, P = I hi/lo, rot hi/lo
    {
        red[tid] = __ldcg(g_Sig + tid*257);
        __syncthreads();
        for (int o = 128; o > 0; o >>= 1) { if (tid < o) red[tid] += red[tid+o]; __syncthreads(); }
        if (tid == 0) { float tr = red[0]; s_scal[0] = 1.f/tr; s_scal[1] = sqrtf(1.f/tr); }
        __syncthreads();
        float sc = s_scal[0];
        int base = cta*1024 + tid*4;
        float4 sg = __ldcg((const float4*)(g_Sig + base));
        float4 rr = __ldcg((const float4*)(rot + base));
        int r = base >> 8, c = base & 255;
        float sv[4] = {sg.x*sc, sg.y*sc, sg.z*sc, sg.w*sc};
        float rv[4] = {rr.x, rr.y, rr.z, rr.w};
        __nv_bfloat16 sh[4], sl[4], rh[4], rl[4], ph[4], pl[4];
        #pragma unroll
        for (int k = 0; k < 4; k++) {
            bfsplit(sv[k], sh[k], sl[k]);
            bfsplit(rv[k], rh[k], rl[k]);
            ph[k] = __float2bfloat16((r == c + k) ? 1.f : 0.f);
            pl[k] = __float2bfloat16(0.f);
        }
        *(__nv_bfloat162*)(g_SNhi + base)     = __nv_bfloat162(sh[0], sh[1]);
        *(__nv_bfloat162*)(g_SNhi + base + 2) = __nv_bfloat162(sh[2], sh[3]);
        *(__nv_bfloat162*)(g_SNlo + base)     = __nv_bfloat162(sl[0], sl[1]);
        *(__nv_bfloat162*)(g_SNlo + base + 2) = __nv_bfloat162(sl[2], sl[3]);
        *(__nv_bfloat162*)(g_Rhi + base)      = __nv_bfloat162(rh[0], rh[1]);
        *(__nv_bfloat162*)(g_Rhi + base + 2)  = __nv_bfloat162(rh[2], rh[3]);
        *(__nv_bfloat162*)(g_Rlo + base)      = __nv_bfloat162(rl[0], rl[1]);
        *(__nv_bfloat162*)(g_Rlo + base + 2)  = __nv_bfloat162(rl[2], rl[3]);
        *(__nv_bfloat162*)(g_Phi + base)      = __nv_bfloat162(ph[0], ph[1]);
        *(__nv_bfloat162*)(g_Phi + base + 2)  = __nv_bfloat162(ph[2], ph[3]);
        *(__nv_bfloat162*)(g_Plo + base)      = __nv_bfloat162(pl[0], pl[1]);
        *(__nv_bfloat162*)(g_Plo + base + 2)  = __nv_bfloat162(pl[2], pl[3]);
    }
    gbar(gb);

    // phase 3: Newton-Schulz on tensor cores — all 64 CTAs busy each phase
    for (int it = 0; it < T_ITERS; it++) {
        if (cta < 32) {
            int t = cta;
            nt_mm2<64>(g_Phi, g_Plo, g_Phi, g_Plo, g_T1hi, g_T1lo,
                       (t >> 3)*64, (t & 7)*32, 0, 0.f, ns);
        } else {
            int t = cta - 32;
            nt_mm2<64>(g_Phi, g_Plo, g_SNhi, g_SNlo, g_T2hi, g_T2lo,
                       (t >> 3)*64, (t & 7)*32, 0, 0.f, ns);
        }
        gbar(gb);
        nt_mm2<32>(g_T1hi, g_T1lo, g_T2hi, g_T2lo, g_Phi, g_Plo,
                   (cta >> 3)*32, (cta & 7)*32, 1, 0.f, ns);
        gbar(gb);
    }

    // phase 4: M = s * rot * P
    nt_mm2<32>(g_Rhi, g_Rlo, g_Phi, g_Plo, g_Mhi, g_Mlo,
               (cta >> 3)*32, (cta & 7)*32, 2, s_scal[1], ns);
    gbar(gb);

    // phase 5: bias
    {
        int wg = cta*8 + wid;
        if (wg < 256) {
            float s = 0.f;
            #pragma unroll
            for (int k = 0; k < 8; k++)
                s += __ldcg(g_M + wg*256 + lane + k*32) * g_mean[lane + k*32];
            #pragma unroll
            for (int o = 16; o > 0; o >>= 1) s += __shfl_xor_sync(~0u, s, o);
            if (lane == 0) g_bias[wg] = s;
        }
    }
}

// ---------------- persistent output GEMM: M resident in smem, X streamed ----------------
#define OMT 18432u
#define OMREG (8u*OMT)
#define OXT 17408u
#define OXSTAGE (2u*OXT)
#define OUT_SMEM (OMREG + 2*OXSTAGE)
__global__ void __launch_bounds__(512, 1) k_out_mma(float* __restrict__ out) {
    extern __shared__ char sm[];
    int tid = threadIdx.x, lane = tid & 31, wid = tid >> 5;
    int wm = wid >> 2, wn = wid & 3;
    uint32_t sbase = smem_u32(sm);
    int cta = blockIdx.x;
    int d0 = (cta & 1) * 128;
    int combo0 = (cta >> 1) * 8;

    int rowA = tid >> 2, qA = tid & 3;
    #pragma unroll
    for (int c = 0; c < 4; c++) {
        uint32_t dA = sbase + c*(2*OMT) + rowA*144 + qA*32;
        const __nv_bfloat16* mh = g_Mhi + (d0 + rowA)*256 + c*64 + qA*16;
        const __nv_bfloat16* ml = g_Mlo + (d0 + rowA)*256 + c*64 + qA*16;
        cp16(dA,            mh);
        cp16(dA + 16,       mh + 8);
        cp16(dA + OMT,      ml);
        cp16(dA + OMT + 16, ml + 8);
    }
    cp_commit();

    int rowB = tid >> 3, qB = tid & 7;
    auto stageX = [&](int g, int st) {
        int combo = combo0 + (g >> 2);
        int n = combo >> 3, p0 = (combo & 7) * 128;
        int cb = (g & 3) * 64;
        uint32_t dB = sbase + OMREG + st*OXSTAGE + rowB*272 + qB*32;
        const __nv_bfloat16* xh = g_xhi + ((size_t)n*CH + cb + rowB)*HW + p0 + qB*16;
        const __nv_bfloat16* xl = g_xlo + ((size_t)n*CH + cb + rowB)*HW + p0 + qB*16;
        cp16(dB,            xh);
        cp16(dB + 16,       xh + 8);
        cp16(dB + OXT,      xl);
        cp16(dB + OXT + 16, xl + 8);
    };

    stageX(0, 0); cp_commit();

    float acc[2][4][4];
    #pragma unroll
    for (int a = 0; a < 2; a++)
        #pragma unroll
        for (int b = 0; b < 4; b++)
            #pragma unroll
            for (int k = 0; k < 4; k++) acc[a][b][k] = 0.f;

    for (int g = 0; g < 32; g++) {
        int cur = g & 1;
        if (g < 31) { stageX(g+1, cur^1); cp_commit(); cp_wait<1>(); }
        else        { cp_wait<0>(); }
        __syncthreads();
        uint32_t sbM = sbase + (g & 3)*(2*OMT);
        uint32_t sbX = sbase + OMREG + cur*OXSTAGE;
        #pragma unroll
        for (int ks = 0; ks < 4; ks++) {
            int k0 = ks*16;
            uint32_t ah[2][4], al[2][4], bh[4][2], bl[4][2];
            int ar = lane & 15, ac = (lane >> 4) * 8;
            #pragma unroll
            for (int mt = 0; mt < 2; mt++) {
                uint32_t ao = sbM + (wm*32 + mt*16 + ar)*144 + (k0 + ac)*2;
                ldm_x4(ah[mt], ao);
                ldm_x4(al[mt], ao + OMT);
            }
            int br = lane & 15;
            #pragma unroll
            for (int nt = 0; nt < 4; nt++) {
                uint32_t bo = sbX + (k0 + br)*272 + (wn*32 + nt*8)*2;
                ldm_x2t(bh[nt], bo);
                ldm_x2t(bl[nt], bo + OXT);
            }
            #pragma unroll
            for (int mt = 0; mt < 2; mt++)
                #pragma unroll
                for (int nt = 0; nt < 4; nt++) {
                    mma_bf16(acc[mt][nt], ah[mt], bh[nt]);
                    mma_bf16(acc[mt][nt], ah[mt], bl[nt]);
                    mma_bf16(acc[mt][nt], al[mt], bh[nt]);
                }
        }
        if ((g & 3) == 3) {
            int combo = combo0 + (g >> 2);
            int n = combo >> 3, p0 = (combo & 7) * 128;
            float* On = out + (size_t)n * (CH*HW);
            int rg = lane >> 2, cg = (lane & 3)*2;
            #pragma unroll
            for (int mt = 0; mt < 2; mt++) {
                int d = d0 + wm*32 + mt*16 + rg;
                float b0 = g_bias[d], b1 = g_bias[d+8];
                #pragma unroll
                for (int nt = 0; nt < 4; nt++) {
                    int p = p0 + wn*32 + nt*8 + cg;
                    *(float2*)(On + (size_t)d*HW + p)     = make_float2(acc[mt][nt][0]-b0, acc[mt][nt][1]-b0);
                    *(float2*)(On + (size_t)(d+8)*HW + p) = make_float2(acc[mt][nt][2]-b1, acc[mt][nt][3]-b1);
                }
            }
            #pragma unroll
            for (int a = 0; a < 2; a++)
                #pragma unroll
                for (int b = 0; b < 4; b++)
                    #pragma unroll
                    for (int k = 0; k < 4; k++) acc[a][b][k] = 0.f;
        }
        __syncthreads();
    }
}

// ---------------- launch ----------------
extern "C" void kernel_launch(void* const* d_in, const int* in_sizes, int n_in,
                              void* d_out, int out_size) {
    const float* X   = (const float*)d_in[0];
    const float* rot = (const float*)d_in[1];
    if (n_in >= 2 && in_sizes[0] == CH*CH && in_sizes[1] != CH*CH) {
        X = (const float*)d_in[1]; rot = (const float*)d_in[0];
    }
    float* out = (float*)d_out;
    (void)out_size;

    cudaFuncSetAttribute(k_gram_fused, cudaFuncAttributeMaxDynamicSharedMemorySize, GF_SMEM);
    cudaFuncSetAttribute(k_out_mma,    cudaFuncAttributeMaxDynamicSharedMemorySize, OUT_SMEM);
    cudaFuncSetAttribute(k_solver,     cudaFuncAttributeMaxDynamicSharedMemorySize, SOLVER_SMEM);

    k_gram_fused<<<dim3(3, 64), 512, GF_SMEM>>>(X);
    k_solver<<<NCTA, 256, SOLVER_SMEM>>>(rot);
    k_out_mma<<<128, 512, OUT_SMEM>>>(out);
}